// round 15
// baseline (speedup 1.0000x reference)
#include <cuda_runtime.h>
#include <cuda_fp16.h>
#include <math.h>
#include <cstdint>

#define S_TOK 4096
#define NH    12
#define HD    64
#define NROWS (S_TOK*NH)
#define QTILE 128
#define KTILE 32
#define NTILES (S_TOK/KTILE)

// SMEM geometry (bytes). Row stride 160B -> conflict-free LDS.64 fragments
#define ROWB   160
#define K_BUF_B (32*ROWB)
#define V_BUF_B (64*ROWB)
#define K_OFF   0
#define V_OFF   (3*K_BUF_B)
#define QF_OFF  (V_OFF + 3*V_BUF_B)
#define SMEM_BYTES (QF_OFF + 128*ROWB)  // 66560 -> 3 CTAs/SM
#define QSTR 76                          // fp32 O-exchange stride (reuses K/V region)

// ---------------- scratch ---------------------------------------------------
__device__ __half g_k[(size_t)NH*S_TOK*HD];   // [h][s][d'] fp16, dims permuted in 16-groups
__device__ __half g_vt[(size_t)NH*HD*S_TOK];  // [h][d][s]  fp16, keys permuted in 16-groups
__device__ float g_P[4][16];
__device__ float g_PT[4][16];
__device__ float g_Pinv[4][16];
__device__ float g_cos[32][8];
__device__ float g_sin[32][8];

__device__ __forceinline__ float ex2(float x) {
    float y; asm("ex2.approx.ftz.f32 %0,%1;" : "=f"(y) : "f"(x)); return y;
}
__device__ __forceinline__ uint32_t smem_u32(const void* p) {
    uint32_t a;
    asm("{ .reg .u64 t; cvta.to.shared.u64 t, %1; cvt.u32.u64 %0, t; }" : "=r"(a) : "l"(p));
    return a;
}
__device__ __forceinline__ void cp16(uint32_t dst, const void* src) {
    asm volatile("cp.async.cg.shared.global [%0], [%1], 16;" :: "r"(dst), "l"(src) : "memory");
}
#define CP_COMMIT() asm volatile("cp.async.commit_group;" ::: "memory")
#define CP_WAIT0()  asm volatile("cp.async.wait_group 0;" ::: "memory")
#define CP_WAIT1()  asm volatile("cp.async.wait_group 1;" ::: "memory")

// pack two fp32 -> fp16x2 (lo, hi)
__device__ __forceinline__ uint32_t packh2(float lo, float hi) {
    uint32_t d; asm("cvt.rn.f16x2.f32 %0, %1, %2;" : "=r"(d) : "f"(hi), "f"(lo)); return d;
}

// m16n8k16 fp16 mma, fp32 accumulate in place
__device__ __forceinline__ void mma_f16(float* d, const uint32_t* a, uint32_t b0, uint32_t b1) {
    asm volatile("mma.sync.aligned.m16n8k16.row.col.f32.f16.f16.f32 "
        "{%0,%1,%2,%3}, {%4,%5,%6,%7}, {%8,%9}, {%0,%1,%2,%3};"
        : "+f"(d[0]), "+f"(d[1]), "+f"(d[2]), "+f"(d[3])
        : "r"(a[0]), "r"(a[1]), "r"(a[2]), "r"(a[3]), "r"(b0), "r"(b1));
}

__device__ __forceinline__ void mm4(const float* A, const float* B, float* Cm) {
#pragma unroll
    for (int i = 0; i < 4; i++)
#pragma unroll
        for (int j = 0; j < 4; j++) {
            float s = 0.f;
#pragma unroll
            for (int kk = 0; kk < 4; kk++) s += A[i*4+kk] * B[kk*4+j];
            Cm[i*4+j] = s;
        }
}

// ---------------------------------------------------------------------------
__global__ void prep_kernel(const float* __restrict__ vm, const float* __restrict__ Ks) {
    int t = threadIdx.x;
    if (t < 32) {
        float L = log2f(100.0f);
#pragma unroll
        for (int i = 0; i < 8; i++) {
            float f = exp2f(-L * (float)i / 8.0f);
            float sv, cv; sincosf((float)t * f, &sv, &cv);
            g_cos[t][i] = cv; g_sin[t][i] = sv;
        }
    }
    if (t < 4) {
        int c = t;
        const float* V  = vm + c*16;
        const float* Kc = Ks + c*9;
        float a = Kc[0] * (1.0f/512.0f);
        float b = Kc[4] * (1.0f/512.0f);
        float u = Kc[2] * (1.0f/512.0f) - 0.5f;
        float w = Kc[5] * (1.0f/512.0f) - 0.5f;
        float K4[16] = {a,0,u,0, 0,b,w,0, 0,0,1,0, 0,0,0,1};
        float Vl[16];
#pragma unroll
        for (int i = 0; i < 16; i++) Vl[i] = V[i];
        float P[16];
        mm4(K4, Vl, P);
#pragma unroll
        for (int i = 0; i < 4; i++)
#pragma unroll
            for (int jj = 0; jj < 4; jj++) { g_P[c][i*4+jj] = P[i*4+jj]; g_PT[c][i*4+jj] = P[jj*4+i]; }
        float Sm[16];
#pragma unroll
        for (int i = 0; i < 3; i++)
#pragma unroll
            for (int jj = 0; jj < 3; jj++) Sm[i*4+jj] = Vl[jj*4+i];
#pragma unroll
        for (int i = 0; i < 3; i++)
            Sm[i*4+3] = -(Sm[i*4+0]*Vl[3] + Sm[i*4+1]*Vl[7] + Sm[i*4+2]*Vl[11]);
        Sm[12]=0.f; Sm[13]=0.f; Sm[14]=0.f; Sm[15]=1.f;
        float Ki[16] = {1.0f/a,0,-u/a,0, 0,1.0f/b,-w/b,0, 0,0,1,0, 0,0,0,1};
        float Pi[16];
        mm4(Sm, Ki, Pi);
#pragma unroll
        for (int i = 0; i < 16; i++) g_Pinv[c][i] = Pi[i];
    }
}

// ---------------------------------------------------------------------------
__device__ __forceinline__ void transform_row_y(
    const float* __restrict__ in, float* __restrict__ y,
    const float* M, int px, int py)
{
    float x[64];
    const float4* in4 = (const float4*)in;
#pragma unroll
    for (int i = 0; i < 16; i++) {
        float4 tv = in4[i];
        x[4*i+0]=tv.x; x[4*i+1]=tv.y; x[4*i+2]=tv.z; x[4*i+3]=tv.w;
    }
#pragma unroll
    for (int g = 0; g < 8; g++)
#pragma unroll
        for (int i = 0; i < 4; i++)
            y[g*4+i] = M[i*4+0]*x[g*4+0] + M[i*4+1]*x[g*4+1]
                     + M[i*4+2]*x[g*4+2] + M[i*4+3]*x[g*4+3];
#pragma unroll
    for (int i = 0; i < 8; i++) {
        float c1 = g_cos[px][i], s1 = g_sin[px][i];
        y[32+i] =  c1*x[32+i] + s1*x[40+i];
        y[40+i] = -s1*x[32+i] + c1*x[40+i];
        float c2 = g_cos[py][i], s2 = g_sin[py][i];
        y[48+i] =  c2*x[48+i] + s2*x[56+i];
        y[56+i] = -s2*x[48+i] + c2*x[56+i];
    }
}

// warp = one 32-token tile of one head (r = h*4096 + s)
__global__ void transform_kv_kernel(const float* __restrict__ k, const float* __restrict__ v) {
    __shared__ __half vsm[8][64][33];
    int tid = threadIdx.x;
    int r = blockIdx.x * 256 + tid;
    int w = tid >> 5, lane = tid & 31;
    int h = r >> 12;
    int s = r & 4095;
    int cam = s >> 10, px = s & 31, py = (s >> 5) & 31;
    float M[16];
#pragma unroll
    for (int i = 0; i < 16; i++) M[i] = g_Pinv[cam][i];
    size_t ibase = ((size_t)s * NH + h) * HD;

    float y[64];
    // ---- K: dim-permuted in 16-groups, fp16, coalesced row store ----
    transform_row_y(k + ibase, y, M, px, py);
    {
        uint32_t kk[32];
#pragma unroll
        for (int t = 0; t < 4; t++)
#pragma unroll
            for (int jj = 0; jj < 4; jj++) {
                int base = t*16, q = t*4 + jj;
                kk[2*q]   = packh2(y[base+2*jj],   y[base+2*jj+1]);
                kk[2*q+1] = packh2(y[base+2*jj+8], y[base+2*jj+9]);
            }
        uint4* o4 = (uint4*)(g_k + ((size_t)h*S_TOK + s)*HD);
#pragma unroll
        for (int i = 0; i < 8; i++) o4[i] = ((uint4*)kk)[i];
    }
    // ---- V: transpose through SMEM -> g_vt[h][d][s], keys permuted in 16-groups ----
    transform_row_y(v + ibase, y, M, px, py);
#pragma unroll
    for (int d = 0; d < 64; d++) vsm[w][d][lane] = __float2half(y[d]);
    __syncwarp();
    int tile = s >> 5;
#pragma unroll
    for (int hf = 0; hf < 2; hf++) {
        int d = lane + 32*hf;
        uint32_t ov[16];
#pragma unroll
        for (int tk = 0; tk < 2; tk++)
#pragma unroll
            for (int q = 0; q < 4; q++) {
                int b = tk*8 + q*2;
                __half2 e = __halves2half2(vsm[w][d][tk*16+2*q],   vsm[w][d][tk*16+2*q+1]);
                __half2 f = __halves2half2(vsm[w][d][tk*16+8+2*q], vsm[w][d][tk*16+8+2*q+1]);
                ov[b]   = *(uint32_t*)&e;
                ov[b+1] = *(uint32_t*)&f;
            }
        uint4* dst = (uint4*)(g_vt + ((size_t)h*HD + d)*S_TOK + (size_t)tile*32);
#pragma unroll
        for (int i = 0; i < 4; i++) dst[i] = ((uint4*)ov)[i];
    }
}

// ---------------------------------------------------------------------------
// fp16 m16n8k16 flash attention, 3 CTAs/SM (register diet: un-pipelined tile
// body; cross-warp occupancy hides the softmax chain). Triple-buffered K/VT.
// ---------------------------------------------------------------------------

#define STAGE(BUF, T) do { \
    uint32_t kb_ = sb + K_OFF + (uint32_t)(BUF) * K_BUF_B; \
    uint32_t vb_ = sb + V_OFF + (uint32_t)(BUF) * V_BUF_B; \
    const __half* ks_ = kg2 + (size_t)(T) * (KTILE*HD); \
    const __half* vs_ = vtg + (size_t)(T) * KTILE; \
    _Pragma("unroll") \
    for (int i_ = 0; i_ < 2; i_++) { \
        int idx_ = tid + i_*128; \
        int kr_ = idx_ >> 3, kc_ = idx_ & 7; \
        cp16(kb_ + (uint32_t)(kr_*ROWB + kc_*16), ks_ + kr_*HD + kc_*8); \
        int vr_ = idx_ >> 2, vc_ = idx_ & 3; \
        cp16(vb_ + (uint32_t)(vr_*ROWB + vc_*16), vs_ + (size_t)vr_*S_TOK + vc_*8); \
    } \
    CP_COMMIT(); \
} while(0)

// SC: f32 scores [2][4][4] -> PH: fp16x2 P fragments [2][4][2]; computes rs
#define SOFTMAX_PK(SC, PH) do { \
    _Pragma("unroll") \
    for (int m_ = 0; m_ < 2; m_++) \
    _Pragma("unroll") \
    for (int hi_ = 0; hi_ < 2; hi_++) { \
        int rc_ = m_*2 + hi_; \
        float mt_ = -1e30f; \
        _Pragma("unroll") \
        for (int nb_ = 0; nb_ < 4; nb_++) { \
            mt_ = fmaxf(mt_, SC[m_][nb_][hi_*2]); \
            mt_ = fmaxf(mt_, SC[m_][nb_][hi_*2+1]); \
        } \
        mt_ = fmaxf(mt_, __shfl_xor_sync(0xffffffffu, mt_, 1)); \
        mt_ = fmaxf(mt_, __shfl_xor_sync(0xffffffffu, mt_, 2)); \
        float mn_ = fmaxf(mrow[rc_], mt_); \
        rs[rc_] = ex2(mrow[rc_] - mn_); \
        mrow[rc_] = mn_; \
        float ps_ = 0.f; \
        _Pragma("unroll") \
        for (int nb_ = 0; nb_ < 4; nb_++) { \
            float p0_ = ex2(SC[m_][nb_][hi_*2]   - mn_); \
            float p1_ = ex2(SC[m_][nb_][hi_*2+1] - mn_); \
            ps_ += p0_ + p1_; \
            PH[m_][nb_][hi_] = packh2(p0_, p1_); \
        } \
        ps_ += __shfl_xor_sync(0xffffffffu, ps_, 1); \
        ps_ += __shfl_xor_sync(0xffffffffu, ps_, 2); \
        lsum[rc_] = lsum[rc_]*rs[rc_] + ps_; \
    } \
} while(0)

#define RESCALE() do { \
    bool a1_ = (rs[0]==1.f) & (rs[1]==1.f) & (rs[2]==1.f) & (rs[3]==1.f); \
    if (!__all_sync(0xffffffffu, a1_)) { \
        _Pragma("unroll") \
        for (int m_ = 0; m_ < 2; m_++) \
        _Pragma("unroll") \
        for (int nb_ = 0; nb_ < 8; nb_++) { \
            o[m_][nb_][0] *= rs[m_*2];   o[m_][nb_][1] *= rs[m_*2]; \
            o[m_][nb_][2] *= rs[m_*2+1]; o[m_][nb_][3] *= rs[m_*2+1]; \
        } \
    } \
} while(0)

#define GEMM1(SCN, KFP) do { \
    _Pragma("unroll") \
    for (int tt_ = 0; tt_ < 4; tt_++) \
    _Pragma("unroll") \
    for (int nb_ = 0; nb_ < 4; nb_++) { \
        uint2 b_ = *(const uint2*)((KFP) + (nb_*8 + g)*ROWB + tt_*32 + 8*j); \
        mma_f16(SCN[0][nb_], qa[0][tt_], b_.x, b_.y); \
        mma_f16(SCN[1][nb_], qa[1][tt_], b_.x, b_.y); \
    } \
} while(0)

#define GEMM2(PH, VFP) do { \
    _Pragma("unroll") \
    for (int tk_ = 0; tk_ < 2; tk_++) { \
        uint32_t pa0_[4] = { PH[0][2*tk_][0], PH[0][2*tk_][1], \
                             PH[0][2*tk_+1][0], PH[0][2*tk_+1][1] }; \
        uint32_t pa1_[4] = { PH[1][2*tk_][0], PH[1][2*tk_][1], \
                             PH[1][2*tk_+1][0], PH[1][2*tk_+1][1] }; \
        _Pragma("unroll") \
        for (int nb_ = 0; nb_ < 8; nb_++) { \
            uint2 b_ = *(const uint2*)((VFP) + (nb_*8 + g)*ROWB + tk_*32 + 8*j); \
            mma_f16(o[0][nb_], pa0_, b_.x, b_.y); \
            mma_f16(o[1][nb_], pa1_, b_.x, b_.y); \
        } \
    } \
} while(0)

__global__ void __launch_bounds__(QTILE, 3)
attn_kernel(const float* __restrict__ q, float* __restrict__ out) {
    extern __shared__ char smraw[];
    const uint32_t sb = smem_u32(smraw);

    const int tid  = threadIdx.x;
    const int w    = tid >> 5, lane = tid & 31;
    const int g    = lane >> 2, j = lane & 3;
    const int h    = blockIdx.y;
    const int s    = blockIdx.x * QTILE + tid;
    const int cam  = s >> 10, px = s & 31, py = (s >> 5) & 31;

    const __half* kg2 = g_k  + (size_t)h * S_TOK * HD;
    const __half* vtg = g_vt + (size_t)h * HD * S_TOK;

    STAGE(0, 0);
    STAGE(1, 1);

    // ---- Q transform -> QF (fp16, dim-permuted, scale*log2e folded) ----
    {
        float y[64];
        transform_row_y(q + (size_t)s * (NH*HD) + (size_t)h * HD, y, g_PT[cam], px, py);
        const float SC = 0.18033688011112042f;  // (1/8)*log2(e)
        uint32_t qq[32];
#pragma unroll
        for (int t = 0; t < 4; t++)
#pragma unroll
            for (int jj = 0; jj < 4; jj++) {
                int base = t*16, qx = t*4 + jj;
                qq[2*qx]   = packh2(y[base+2*jj]*SC,   y[base+2*jj+1]*SC);
                qq[2*qx+1] = packh2(y[base+2*jj+8]*SC, y[base+2*jj+9]*SC);
            }
        uint4* dst = (uint4*)(smraw + QF_OFF + tid*ROWB);
#pragma unroll
        for (int i = 0; i < 8; i++) dst[i] = ((uint4*)qq)[i];
    }
    CP_WAIT1();
    __syncthreads();

    // ---- persistent Q A-fragments (LDS.64 pairs) ----
    uint32_t qa[2][4][4];
#pragma unroll
    for (int m = 0; m < 2; m++)
#pragma unroll
        for (int tt = 0; tt < 4; tt++) {
            const char* rp = smraw + QF_OFF + (w*32 + m*16 + g)*ROWB + tt*32 + 8*j;
            uint2 lo = *(const uint2*)rp;
            uint2 hi = *(const uint2*)(rp + 8*ROWB);
            qa[m][tt][0] = lo.x; qa[m][tt][1] = hi.x;
            qa[m][tt][2] = lo.y; qa[m][tt][3] = hi.y;
        }

    float o[2][8][4];
#pragma unroll
    for (int m = 0; m < 2; m++)
#pragma unroll
        for (int nb = 0; nb < 8; nb++)
#pragma unroll
            for (int e = 0; e < 4; e++) o[m][nb][e] = 0.f;
    float mrow[4] = {-1e30f, -1e30f, -1e30f, -1e30f};
    float lsum[4] = {0.f, 0.f, 0.f, 0.f};
    float rs[4];
    float sc[2][4][4];
    uint32_t ph[2][4][2];
    int bc = 0, bn = 1, bf = 2;

    // ---- main loop: un-pipelined body; occupancy (3 warps/SMSP) hides chain
#pragma unroll 1
    for (int t = 0; t < NTILES; t++) {
        CP_WAIT0();
        __syncthreads();
        if (t + 2 < NTILES) STAGE(bf, t + 2);
        const char* Kf = smraw + K_OFF + bc*K_BUF_B;
        const char* Vf = smraw + V_OFF + bc*V_BUF_B;
#pragma unroll
        for (int m = 0; m < 2; m++)
#pragma unroll
            for (int nb = 0; nb < 4; nb++)
#pragma unroll
                for (int e = 0; e < 4; e++) sc[m][nb][e] = 0.f;
        GEMM1(sc, Kf);
        SOFTMAX_PK(sc, ph);
        RESCALE();
        GEMM2(ph, Vf);
        int tb = bc; bc = bn; bn = bf; bf = tb;
    }

    // ---- normalize, exchange O through SMEM (reuse K/V region), epilogue ----
    __syncthreads();
    float* QP = (float*)smraw;
    float inv[4];
#pragma unroll
    for (int rc = 0; rc < 4; rc++) inv[rc] = 1.0f / lsum[rc];
#pragma unroll
    for (int m = 0; m < 2; m++) {
        int r0 = w*32 + m*16 + g, r1 = r0 + 8;
#pragma unroll
        for (int nb = 0; nb < 8; nb++) {
            *(float2*)&QP[r0*QSTR + nb*8 + 2*j] =
                make_float2(o[m][nb][0]*inv[m*2],   o[m][nb][1]*inv[m*2]);
            *(float2*)&QP[r1*QSTR + nb*8 + 2*j] =
                make_float2(o[m][nb][2]*inv[m*2+1], o[m][nb][3]*inv[m*2+1]);
        }
    }
    __syncthreads();

    {
        float acc[64];
#pragma unroll
        for (int i = 0; i < 16; i++) {
            float4 tv = *(const float4*)&QP[(size_t)tid*QSTR + i*4];
            acc[4*i+0]=tv.x; acc[4*i+1]=tv.y; acc[4*i+2]=tv.z; acc[4*i+3]=tv.w;
        }
        float y[64];
        const float* M = g_P[cam];
#pragma unroll
        for (int gg = 0; gg < 8; gg++)
#pragma unroll
            for (int i = 0; i < 4; i++)
                y[gg*4+i] = M[i*4+0]*acc[gg*4+0] + M[i*4+1]*acc[gg*4+1]
                          + M[i*4+2]*acc[gg*4+2] + M[i*4+3]*acc[gg*4+3];
#pragma unroll
        for (int i = 0; i < 8; i++) {
            float c1 = g_cos[px][i], s1 = g_sin[px][i];
            y[32+i] = c1*acc[32+i] - s1*acc[40+i];
            y[40+i] = s1*acc[32+i] + c1*acc[40+i];
            float c2 = g_cos[py][i], s2 = g_sin[py][i];
            y[48+i] = c2*acc[48+i] - s2*acc[56+i];
            y[56+i] = s2*acc[48+i] + c2*acc[56+i];
        }
        float4* o4 = (float4*)(out + (size_t)s * (NH*HD) + (size_t)h * HD);
#pragma unroll
        for (int i = 0; i < 16; i++)
            o4[i] = make_float4(y[4*i+0], y[4*i+1], y[4*i+2], y[4*i+3]);
    }
}

// ---------------------------------------------------------------------------
extern "C" void kernel_launch(void* const* d_in, const int* in_sizes, int n_in,
                              void* d_out, int out_size) {
    const float* q  = (const float*)d_in[0];
    const float* k  = (const float*)d_in[1];
    const float* v  = (const float*)d_in[2];
    const float* vm = (const float*)d_in[3];
    const float* Ks = (const float*)d_in[4];
    float* out = (float*)d_out;

    cudaFuncSetAttribute(attn_kernel, cudaFuncAttributeMaxDynamicSharedMemorySize, SMEM_BYTES);

    prep_kernel<<<1, 32>>>(vm, Ks);
    transform_kv_kernel<<<NROWS / 256, 256>>>(k, v);
    attn_kernel<<<dim3(S_TOK / QTILE, NH), QTILE, SMEM_BYTES>>>(q, out);
}

// round 16
// speedup vs baseline: 1.0185x; 1.0185x over previous
#include <cuda_runtime.h>
#include <cuda_fp16.h>
#include <math.h>
#include <cstdint>

#define S_TOK 4096
#define NH    12
#define HD    64
#define NROWS (S_TOK*NH)
#define QTILE 128
#define KTILE 32
#define NTILES (S_TOK/KTILE)

// SMEM geometry (bytes). Row stride 160B -> conflict-free LDS.64 fragments
#define ROWB   160
#define K_BUF_B (32*ROWB)               // 5120
#define V_BUF_B (64*ROWB)               // 10240
#define K_OFF   0
#define V_OFF   (4*K_BUF_B)             // 20480
#define QF_OFF  (V_OFF + 4*V_BUF_B)     // 61440
#define SMEM_BYTES (QF_OFF + 128*ROWB)  // 81920 -> 2 CTAs/SM
#define QSTR 76                          // fp32 O-exchange stride (reuses K/V region)

// ---------------- scratch ---------------------------------------------------
__device__ __half g_k[(size_t)NH*S_TOK*HD];   // [h][s][d'] fp16, dims permuted in 16-groups
__device__ __half g_vt[(size_t)NH*HD*S_TOK];  // [h][d][s]  fp16, keys permuted in 16-groups
__device__ float g_P[4][16];
__device__ float g_PT[4][16];
__device__ float g_Pinv[4][16];
__device__ float g_cos[32][8];
__device__ float g_sin[32][8];

__device__ __forceinline__ float ex2(float x) {
    float y; asm("ex2.approx.ftz.f32 %0,%1;" : "=f"(y) : "f"(x)); return y;
}
__device__ __forceinline__ uint32_t smem_u32(const void* p) {
    uint32_t a;
    asm("{ .reg .u64 t; cvta.to.shared.u64 t, %1; cvt.u32.u64 %0, t; }" : "=r"(a) : "l"(p));
    return a;
}
__device__ __forceinline__ void cp16(uint32_t dst, const void* src) {
    asm volatile("cp.async.cg.shared.global [%0], [%1], 16;" :: "r"(dst), "l"(src) : "memory");
}
#define CP_COMMIT() asm volatile("cp.async.commit_group;" ::: "memory")
#define CP_WAIT1()  asm volatile("cp.async.wait_group 1;" ::: "memory")
#define CP_WAIT2()  asm volatile("cp.async.wait_group 2;" ::: "memory")

// pack two fp32 -> fp16x2 (lo, hi)
__device__ __forceinline__ uint32_t packh2(float lo, float hi) {
    uint32_t d; asm("cvt.rn.f16x2.f32 %0, %1, %2;" : "=r"(d) : "f"(hi), "f"(lo)); return d;
}

// m16n8k16 fp16 mma, fp32 accumulate in place
__device__ __forceinline__ void mma_f16(float* d, const uint32_t* a, uint32_t b0, uint32_t b1) {
    asm volatile("mma.sync.aligned.m16n8k16.row.col.f32.f16.f16.f32 "
        "{%0,%1,%2,%3}, {%4,%5,%6,%7}, {%8,%9}, {%0,%1,%2,%3};"
        : "+f"(d[0]), "+f"(d[1]), "+f"(d[2]), "+f"(d[3])
        : "r"(a[0]), "r"(a[1]), "r"(a[2]), "r"(a[3]), "r"(b0), "r"(b1));
}

__device__ __forceinline__ void mm4(const float* A, const float* B, float* Cm) {
#pragma unroll
    for (int i = 0; i < 4; i++)
#pragma unroll
        for (int j = 0; j < 4; j++) {
            float s = 0.f;
#pragma unroll
            for (int kk = 0; kk < 4; kk++) s += A[i*4+kk] * B[kk*4+j];
            Cm[i*4+j] = s;
        }
}

// ---------------------------------------------------------------------------
__global__ void prep_kernel(const float* __restrict__ vm, const float* __restrict__ Ks) {
    int t = threadIdx.x;
    // 256 threads: one sincosf each (pos = t>>3, freq index = t&7)
    {
        int pos = t >> 3, i = t & 7;
        float L = log2f(100.0f);
        float f = exp2f(-L * (float)i / 8.0f);
        float sv, cv; sincosf((float)pos * f, &sv, &cv);
        g_cos[pos][i] = cv; g_sin[pos][i] = sv;
    }
    if (t < 4) {
        int c = t;
        const float* V  = vm + c*16;
        const float* Kc = Ks + c*9;
        float a = Kc[0] * (1.0f/512.0f);
        float b = Kc[4] * (1.0f/512.0f);
        float u = Kc[2] * (1.0f/512.0f) - 0.5f;
        float w = Kc[5] * (1.0f/512.0f) - 0.5f;
        float K4[16] = {a,0,u,0, 0,b,w,0, 0,0,1,0, 0,0,0,1};
        float Vl[16];
#pragma unroll
        for (int i = 0; i < 16; i++) Vl[i] = V[i];
        float P[16];
        mm4(K4, Vl, P);
#pragma unroll
        for (int i = 0; i < 4; i++)
#pragma unroll
            for (int jj = 0; jj < 4; jj++) { g_P[c][i*4+jj] = P[i*4+jj]; g_PT[c][i*4+jj] = P[jj*4+i]; }
        float Sm[16];
#pragma unroll
        for (int i = 0; i < 3; i++)
#pragma unroll
            for (int jj = 0; jj < 3; jj++) Sm[i*4+jj] = Vl[jj*4+i];
#pragma unroll
        for (int i = 0; i < 3; i++)
            Sm[i*4+3] = -(Sm[i*4+0]*Vl[3] + Sm[i*4+1]*Vl[7] + Sm[i*4+2]*Vl[11]);
        Sm[12]=0.f; Sm[13]=0.f; Sm[14]=0.f; Sm[15]=1.f;
        float Ki[16] = {1.0f/a,0,-u/a,0, 0,1.0f/b,-w/b,0, 0,0,1,0, 0,0,0,1};
        float Pi[16];
        mm4(Sm, Ki, Pi);
#pragma unroll
        for (int i = 0; i < 16; i++) g_Pinv[c][i] = Pi[i];
    }
}

// ---------------------------------------------------------------------------
__device__ __forceinline__ void transform_row_y(
    const float* __restrict__ in, float* __restrict__ y,
    const float* M, int px, int py)
{
    float x[64];
    const float4* in4 = (const float4*)in;
#pragma unroll
    for (int i = 0; i < 16; i++) {
        float4 tv = in4[i];
        x[4*i+0]=tv.x; x[4*i+1]=tv.y; x[4*i+2]=tv.z; x[4*i+3]=tv.w;
    }
#pragma unroll
    for (int g = 0; g < 8; g++)
#pragma unroll
        for (int i = 0; i < 4; i++)
            y[g*4+i] = M[i*4+0]*x[g*4+0] + M[i*4+1]*x[g*4+1]
                     + M[i*4+2]*x[g*4+2] + M[i*4+3]*x[g*4+3];
#pragma unroll
    for (int i = 0; i < 8; i++) {
        float c1 = g_cos[px][i], s1 = g_sin[px][i];
        y[32+i] =  c1*x[32+i] + s1*x[40+i];
        y[40+i] = -s1*x[32+i] + c1*x[40+i];
        float c2 = g_cos[py][i], s2 = g_sin[py][i];
        y[48+i] =  c2*x[48+i] + s2*x[56+i];
        y[56+i] = -s2*x[48+i] + c2*x[56+i];
    }
}

// warp = one 32-token tile of one head (r = h*4096 + s)
__global__ void transform_kv_kernel(const float* __restrict__ k, const float* __restrict__ v) {
    __shared__ __half vsm[8][64][33];
    int tid = threadIdx.x;
    int r = blockIdx.x * 256 + tid;
    int w = tid >> 5, lane = tid & 31;
    int h = r >> 12;
    int s = r & 4095;
    int cam = s >> 10, px = s & 31, py = (s >> 5) & 31;
    float M[16];
#pragma unroll
    for (int i = 0; i < 16; i++) M[i] = g_Pinv[cam][i];
    size_t ibase = ((size_t)s * NH + h) * HD;

    float y[64];
    // ---- K: dim-permuted in 16-groups, fp16, coalesced row store ----
    transform_row_y(k + ibase, y, M, px, py);
    {
        uint32_t kk[32];
#pragma unroll
        for (int t = 0; t < 4; t++)
#pragma unroll
            for (int jj = 0; jj < 4; jj++) {
                int base = t*16, q = t*4 + jj;
                kk[2*q]   = packh2(y[base+2*jj],   y[base+2*jj+1]);
                kk[2*q+1] = packh2(y[base+2*jj+8], y[base+2*jj+9]);
            }
        uint4* o4 = (uint4*)(g_k + ((size_t)h*S_TOK + s)*HD);
#pragma unroll
        for (int i = 0; i < 8; i++) o4[i] = ((uint4*)kk)[i];
    }
    // ---- V: transpose through SMEM -> g_vt[h][d][s], keys permuted in 16-groups ----
    transform_row_y(v + ibase, y, M, px, py);
#pragma unroll
    for (int d = 0; d < 64; d++) vsm[w][d][lane] = __float2half(y[d]);
    __syncwarp();
    int tile = s >> 5;
#pragma unroll
    for (int hf = 0; hf < 2; hf++) {
        int d = lane + 32*hf;
        uint32_t ov[16];
#pragma unroll
        for (int tk = 0; tk < 2; tk++)
#pragma unroll
            for (int q = 0; q < 4; q++) {
                int b = tk*8 + q*2;
                __half2 e = __halves2half2(vsm[w][d][tk*16+2*q],   vsm[w][d][tk*16+2*q+1]);
                __half2 f = __halves2half2(vsm[w][d][tk*16+8+2*q], vsm[w][d][tk*16+8+2*q+1]);
                ov[b]   = *(uint32_t*)&e;
                ov[b+1] = *(uint32_t*)&f;
            }
        uint4* dst = (uint4*)(g_vt + ((size_t)h*HD + d)*S_TOK + (size_t)tile*32);
#pragma unroll
        for (int i = 0; i < 4; i++) dst[i] = ((uint4*)ov)[i];
    }
}

// ---------------------------------------------------------------------------
// fp16 m16n8k16 pipelined flash attention; quad-buffered K/VT with
// wait_group 1 (consumed tiles are 2 iterations old -> cp.async fully hidden).
// ---------------------------------------------------------------------------

#define STAGE(BUF, T) do { \
    uint32_t kb_ = sb + K_OFF + (uint32_t)(BUF) * K_BUF_B; \
    uint32_t vb_ = sb + V_OFF + (uint32_t)(BUF) * V_BUF_B; \
    const __half* ks_ = kg2 + (size_t)(T) * (KTILE*HD); \
    const __half* vs_ = vtg + (size_t)(T) * KTILE; \
    _Pragma("unroll") \
    for (int i_ = 0; i_ < 2; i_++) { \
        int idx_ = tid + i_*128; \
        int kr_ = idx_ >> 3, kc_ = idx_ & 7; \
        cp16(kb_ + (uint32_t)(kr_*ROWB + kc_*16), ks_ + kr_*HD + kc_*8); \
        int vr_ = idx_ >> 2, vc_ = idx_ & 3; \
        cp16(vb_ + (uint32_t)(vr_*ROWB + vc_*16), vs_ + (size_t)vr_*S_TOK + vc_*8); \
    } \
    CP_COMMIT(); \
} while(0)

// SC: f32 scores [2][4][4] -> PH: fp16x2 P fragments [2][4][2]; computes rs
#define SOFTMAX_PK(SC, PH) do { \
    _Pragma("unroll") \
    for (int m_ = 0; m_ < 2; m_++) \
    _Pragma("unroll") \
    for (int hi_ = 0; hi_ < 2; hi_++) { \
        int rc_ = m_*2 + hi_; \
        float mt_ = -1e30f; \
        _Pragma("unroll") \
        for (int nb_ = 0; nb_ < 4; nb_++) { \
            mt_ = fmaxf(mt_, SC[m_][nb_][hi_*2]); \
            mt_ = fmaxf(mt_, SC[m_][nb_][hi_*2+1]); \
        } \
        mt_ = fmaxf(mt_, __shfl_xor_sync(0xffffffffu, mt_, 1)); \
        mt_ = fmaxf(mt_, __shfl_xor_sync(0xffffffffu, mt_, 2)); \
        float mn_ = fmaxf(mrow[rc_], mt_); \
        rs[rc_] = ex2(mrow[rc_] - mn_); \
        mrow[rc_] = mn_; \
        float ps_ = 0.f; \
        _Pragma("unroll") \
        for (int nb_ = 0; nb_ < 4; nb_++) { \
            float p0_ = ex2(SC[m_][nb_][hi_*2]   - mn_); \
            float p1_ = ex2(SC[m_][nb_][hi_*2+1] - mn_); \
            ps_ += p0_ + p1_; \
            PH[m_][nb_][hi_] = packh2(p0_, p1_); \
        } \
        ps_ += __shfl_xor_sync(0xffffffffu, ps_, 1); \
        ps_ += __shfl_xor_sync(0xffffffffu, ps_, 2); \
        lsum[rc_] = lsum[rc_]*rs[rc_] + ps_; \
    } \
} while(0)

#define RESCALE() do { \
    bool a1_ = (rs[0]==1.f) & (rs[1]==1.f) & (rs[2]==1.f) & (rs[3]==1.f); \
    if (!__all_sync(0xffffffffu, a1_)) { \
        _Pragma("unroll") \
        for (int m_ = 0; m_ < 2; m_++) \
        _Pragma("unroll") \
        for (int nb_ = 0; nb_ < 8; nb_++) { \
            o[m_][nb_][0] *= rs[m_*2];   o[m_][nb_][1] *= rs[m_*2]; \
            o[m_][nb_][2] *= rs[m_*2+1]; o[m_][nb_][3] *= rs[m_*2+1]; \
        } \
    } \
} while(0)

#define GEMM1(SCN, KFP) do { \
    _Pragma("unroll") \
    for (int tt_ = 0; tt_ < 4; tt_++) \
    _Pragma("unroll") \
    for (int nb_ = 0; nb_ < 4; nb_++) { \
        uint2 b_ = *(const uint2*)((KFP) + (nb_*8 + g)*ROWB + tt_*32 + 8*j); \
        mma_f16(SCN[0][nb_], qa[0][tt_], b_.x, b_.y); \
        mma_f16(SCN[1][nb_], qa[1][tt_], b_.x, b_.y); \
    } \
} while(0)

#define GEMM2(PH, VFP) do { \
    _Pragma("unroll") \
    for (int tk_ = 0; tk_ < 2; tk_++) { \
        uint32_t pa0_[4] = { PH[0][2*tk_][0], PH[0][2*tk_][1], \
                             PH[0][2*tk_+1][0], PH[0][2*tk_+1][1] }; \
        uint32_t pa1_[4] = { PH[1][2*tk_][0], PH[1][2*tk_][1], \
                             PH[1][2*tk_+1][0], PH[1][2*tk_+1][1] }; \
        _Pragma("unroll") \
        for (int nb_ = 0; nb_ < 8; nb_++) { \
            uint2 b_ = *(const uint2*)((VFP) + (nb_*8 + g)*ROWB + tk_*32 + 8*j); \
            mma_f16(o[0][nb_], pa0_, b_.x, b_.y); \
            mma_f16(o[1][nb_], pa1_, b_.x, b_.y); \
        } \
    } \
} while(0)

// body(t): GEMM1(t+1) from buf bn, GEMM2(t) from buf bc, stage t+3 into bg.
// CP_WAIT1 leaves only the newest group (t+2) outstanding -> stage(t+1) done.
#define TILE_BODY(T, PHP, PHN) do { \
    CP_WAIT1(); __syncthreads(); \
    if ((T)+3 < NTILES) STAGE(bg, (T)+3); \
    const char* Kf_ = smraw + K_OFF + bn*K_BUF_B; \
    const char* Vf_ = smraw + V_OFF + bc*V_BUF_B; \
    _Pragma("unroll") \
    for (int m_ = 0; m_ < 2; m_++) \
    _Pragma("unroll") \
    for (int nb_ = 0; nb_ < 4; nb_++) \
    _Pragma("unroll") \
    for (int e_ = 0; e_ < 4; e_++) sc[m_][nb_][e_] = 0.f; \
    GEMM1(sc, Kf_); \
    RESCALE(); \
    SOFTMAX_PK(sc, PHN); \
    GEMM2(PHP, Vf_); \
    { int tb_ = bc; bc = bn; bn = bf; bf = bg; bg = tb_; } \
} while(0)

__global__ void __launch_bounds__(QTILE)
attn_kernel(const float* __restrict__ q, float* __restrict__ out) {
    extern __shared__ char smraw[];
    const uint32_t sb = smem_u32(smraw);

    const int tid  = threadIdx.x;
    const int w    = tid >> 5, lane = tid & 31;
    const int g    = lane >> 2, j = lane & 3;
    const int h    = blockIdx.y;
    const int s    = blockIdx.x * QTILE + tid;
    const int cam  = s >> 10, px = s & 31, py = (s >> 5) & 31;

    const __half* kg2 = g_k  + (size_t)h * S_TOK * HD;
    const __half* vtg = g_vt + (size_t)h * HD * S_TOK;

    STAGE(0, 0);
    STAGE(1, 1);
    STAGE(2, 2);

    // ---- Q transform -> QF (fp16, dim-permuted, scale*log2e folded) ----
    {
        float y[64];
        transform_row_y(q + (size_t)s * (NH*HD) + (size_t)h * HD, y, g_PT[cam], px, py);
        const float SC = 0.18033688011112042f;  // (1/8)*log2(e)
        uint32_t qq[32];
#pragma unroll
        for (int t = 0; t < 4; t++)
#pragma unroll
            for (int jj = 0; jj < 4; jj++) {
                int base = t*16, qx = t*4 + jj;
                qq[2*qx]   = packh2(y[base+2*jj]*SC,   y[base+2*jj+1]*SC);
                qq[2*qx+1] = packh2(y[base+2*jj+8]*SC, y[base+2*jj+9]*SC);
            }
        uint4* dst = (uint4*)(smraw + QF_OFF + tid*ROWB);
#pragma unroll
        for (int i = 0; i < 8; i++) dst[i] = ((uint4*)qq)[i];
    }
    CP_WAIT2();      // tile 0 ready; tiles 1,2 still in flight
    __syncthreads();

    // ---- persistent Q A-fragments (LDS.64 pairs) ----
    uint32_t qa[2][4][4];
#pragma unroll
    for (int m = 0; m < 2; m++)
#pragma unroll
        for (int tt = 0; tt < 4; tt++) {
            const char* rp = smraw + QF_OFF + (w*32 + m*16 + g)*ROWB + tt*32 + 8*j;
            uint2 lo = *(const uint2*)rp;
            uint2 hi = *(const uint2*)(rp + 8*ROWB);
            qa[m][tt][0] = lo.x; qa[m][tt][1] = hi.x;
            qa[m][tt][2] = lo.y; qa[m][tt][3] = hi.y;
        }

    float o[2][8][4];
#pragma unroll
    for (int m = 0; m < 2; m++)
#pragma unroll
        for (int nb = 0; nb < 8; nb++)
#pragma unroll
            for (int e = 0; e < 4; e++) o[m][nb][e] = 0.f;
    float mrow[4] = {-1e30f, -1e30f, -1e30f, -1e30f};
    float lsum[4] = {0.f, 0.f, 0.f, 0.f};
    float rs[4];
    float sc[2][4][4];
    uint32_t phA[2][4][2], phB[2][4][2];
    int bc = 0, bn = 1, bf = 2, bg = 3;

    // ---- preamble: GEMM1(0) + softmax(0) into phA ----
    {
        const char* Kf_ = smraw + K_OFF;
#pragma unroll
        for (int m = 0; m < 2; m++)
#pragma unroll
            for (int nb = 0; nb < 4; nb++)
#pragma unroll
                for (int e = 0; e < 4; e++) sc[m][nb][e] = 0.f;
        GEMM1(sc, Kf_);
        SOFTMAX_PK(sc, phA);
    }

    // ---- pipelined main loop (127 bodies) ----
#pragma unroll 1
    for (int t = 0; t < NTILES-2; t += 2) {
        TILE_BODY(t,   phA, phB);
        TILE_BODY(t+1, phB, phA);
    }
    TILE_BODY(NTILES-2, phA, phB);

    // ---- final tile: rescale + GEMM2(127) ----
    {
        const char* Vf_ = smraw + V_OFF + bc*V_BUF_B;
        RESCALE();
        GEMM2(phB, Vf_);
    }

    // ---- normalize, exchange O through SMEM (reuse K/V region), epilogue ----
    __syncthreads();
    float* QP = (float*)smraw;
    float inv[4];
#pragma unroll
    for (int rc = 0; rc < 4; rc++) inv[rc] = 1.0f / lsum[rc];
#pragma unroll
    for (int m = 0; m < 2; m++) {
        int r0 = w*32 + m*16 + g, r1 = r0 + 8;
#pragma unroll
        for (int nb = 0; nb < 8; nb++) {
            *(float2*)&QP[r0*QSTR + nb*8 + 2*j] =
                make_float2(o[m][nb][0]*inv[m*2],   o[m][nb][1]*inv[m*2]);
            *(float2*)&QP[r1*QSTR + nb*8 + 2*j] =
                make_float2(o[m][nb][2]*inv[m*2+1], o[m][nb][3]*inv[m*2+1]);
        }
    }
    __syncthreads();

    {
        float acc[64];
#pragma unroll
        for (int i = 0; i < 16; i++) {
            float4 tv = *(const float4*)&QP[(size_t)tid*QSTR + i*4];
            acc[4*i+0]=tv.x; acc[4*i+1]=tv.y; acc[4*i+2]=tv.z; acc[4*i+3]=tv.w;
        }
        float y[64];
        const float* M = g_P[cam];
#pragma unroll
        for (int gg = 0; gg < 8; gg++)
#pragma unroll
            for (int i = 0; i < 4; i++)
                y[gg*4+i] = M[i*4+0]*acc[gg*4+0] + M[i*4+1]*acc[gg*4+1]
                          + M[i*4+2]*acc[gg*4+2] + M[i*4+3]*acc[gg*4+3];
#pragma unroll
        for (int i = 0; i < 8; i++) {
            float c1 = g_cos[px][i], s1 = g_sin[px][i];
            y[32+i] = c1*acc[32+i] - s1*acc[40+i];
            y[40+i] = s1*acc[32+i] + c1*acc[40+i];
            float c2 = g_cos[py][i], s2 = g_sin[py][i];
            y[48+i] = c2*acc[48+i] - s2*acc[56+i];
            y[56+i] = s2*acc[48+i] + c2*acc[56+i];
        }
        float4* o4 = (float4*)(out + (size_t)s * (NH*HD) + (size_t)h * HD);
#pragma unroll
        for (int i = 0; i < 16; i++)
            o4[i] = make_float4(y[4*i+0], y[4*i+1], y[4*i+2], y[4*i+3]);
    }
}

// ---------------------------------------------------------------------------
extern "C" void kernel_launch(void* const* d_in, const int* in_sizes, int n_in,
                              void* d_out, int out_size) {
    const float* q  = (const float*)d_in[0];
    const float* k  = (const float*)d_in[1];
    const float* v  = (const float*)d_in[2];
    const float* vm = (const float*)d_in[3];
    const float* Ks = (const float*)d_in[4];
    float* out = (float*)d_out;

    cudaFuncSetAttribute(attn_kernel, cudaFuncAttributeMaxDynamicSharedMemorySize, SMEM_BYTES);

    prep_kernel<<<1, 256>>>(vm, Ks);
    transform_kv_kernel<<<NROWS / 256, 256>>>(k, v);
    attn_kernel<<<dim3(S_TOK / QTILE, NH), QTILE, SMEM_BYTES>>>(q, out);
}

// round 17
// speedup vs baseline: 1.0537x; 1.0346x over previous
#include <cuda_runtime.h>
#include <cuda_fp16.h>
#include <math.h>
#include <cstdint>

#define S_TOK 4096
#define NH    12
#define HD    64
#define NROWS (S_TOK*NH)
#define QTILE 128
#define KTILE 32
#define NTILES (S_TOK/KTILE)

// SMEM geometry (bytes). Row stride 160B -> conflict-free LDS.64 fragments
#define ROWB   160
#define K_BUF_B (32*ROWB)
#define V_BUF_B (64*ROWB)
#define K_OFF   0
#define V_OFF   (3*K_BUF_B)
#define QF_OFF  (V_OFF + 3*V_BUF_B)
#define SMEM_BYTES (QF_OFF + 128*ROWB)  // 66560
#define QSTR 76                          // fp32 O-exchange stride (reuses K/V region)

// ---------------- scratch ---------------------------------------------------
__device__ __half g_k[(size_t)NH*S_TOK*HD];   // [h][s][d'] fp16, dims permuted in 16-groups
__device__ __half g_vt[(size_t)NH*HD*S_TOK];  // [h][d][s]  fp16, keys permuted in 16-groups
__device__ float g_P[4][16];
__device__ float g_PT[4][16];
__device__ float g_cos[32][8];
__device__ float g_sin[32][8];

__device__ __forceinline__ float ex2(float x) {
    float y; asm("ex2.approx.ftz.f32 %0,%1;" : "=f"(y) : "f"(x)); return y;
}
__device__ __forceinline__ uint32_t smem_u32(const void* p) {
    uint32_t a;
    asm("{ .reg .u64 t; cvta.to.shared.u64 t, %1; cvt.u32.u64 %0, t; }" : "=r"(a) : "l"(p));
    return a;
}
__device__ __forceinline__ void cp16(uint32_t dst, const void* src) {
    asm volatile("cp.async.cg.shared.global [%0], [%1], 16;" :: "r"(dst), "l"(src) : "memory");
}
#define CP_COMMIT() asm volatile("cp.async.commit_group;" ::: "memory")
#define CP_WAIT0()  asm volatile("cp.async.wait_group 0;" ::: "memory")
#define CP_WAIT1()  asm volatile("cp.async.wait_group 1;" ::: "memory")

// pack two fp32 -> fp16x2 (lo, hi)
__device__ __forceinline__ uint32_t packh2(float lo, float hi) {
    uint32_t d; asm("cvt.rn.f16x2.f32 %0, %1, %2;" : "=r"(d) : "f"(hi), "f"(lo)); return d;
}

// m16n8k16 fp16 mma, fp32 accumulate in place
__device__ __forceinline__ void mma_f16(float* d, const uint32_t* a, uint32_t b0, uint32_t b1) {
    asm volatile("mma.sync.aligned.m16n8k16.row.col.f32.f16.f16.f32 "
        "{%0,%1,%2,%3}, {%4,%5,%6,%7}, {%8,%9}, {%0,%1,%2,%3};"
        : "+f"(d[0]), "+f"(d[1]), "+f"(d[2]), "+f"(d[3])
        : "r"(a[0]), "r"(a[1]), "r"(a[2]), "r"(a[3]), "r"(b0), "r"(b1));
}

__device__ __forceinline__ void mm4(const float* A, const float* B, float* Cm) {
#pragma unroll
    for (int i = 0; i < 4; i++)
#pragma unroll
        for (int j = 0; j < 4; j++) {
            float s = 0.f;
#pragma unroll
            for (int kk = 0; kk < 4; kk++) s += A[i*4+kk] * B[kk*4+j];
            Cm[i*4+j] = s;
        }
}

// ---------------------------------------------------------------------------
// Row transform with caller-provided tables (shared or global)
__device__ __forceinline__ void transform_row_t(
    const float* __restrict__ in, float* __restrict__ y,
    const float* M, const float (*cosp)[8], const float (*sinp)[8],
    int px, int py)
{
    float x[64];
    const float4* in4 = (const float4*)in;
#pragma unroll
    for (int i = 0; i < 16; i++) {
        float4 tv = in4[i];
        x[4*i+0]=tv.x; x[4*i+1]=tv.y; x[4*i+2]=tv.z; x[4*i+3]=tv.w;
    }
#pragma unroll
    for (int g = 0; g < 8; g++)
#pragma unroll
        for (int i = 0; i < 4; i++)
            y[g*4+i] = M[i*4+0]*x[g*4+0] + M[i*4+1]*x[g*4+1]
                     + M[i*4+2]*x[g*4+2] + M[i*4+3]*x[g*4+3];
#pragma unroll
    for (int i = 0; i < 8; i++) {
        float c1 = cosp[px][i], s1 = sinp[px][i];
        y[32+i] =  c1*x[32+i] + s1*x[40+i];
        y[40+i] = -s1*x[32+i] + c1*x[40+i];
        float c2 = cosp[py][i], s2 = sinp[py][i];
        y[48+i] =  c2*x[48+i] + s2*x[56+i];
        y[56+i] = -s2*x[48+i] + c2*x[56+i];
    }
}

// ---------------------------------------------------------------------------
// Fused prep + transform. Each block (256 thr) builds the RoPE table and the
// 4 camera matrices in SMEM; block 0 also publishes the attn kernel's tables.
// warp = one 32-token tile of one head (r = h*4096 + s)
__global__ void transform_kv_kernel(const float* __restrict__ k, const float* __restrict__ v,
                                    const float* __restrict__ vm, const float* __restrict__ Ks) {
    __shared__ __half vsm[8][64][33];
    __shared__ float sPinv[4][16];
    __shared__ float sCos[32][8], sSin[32][8];

    int tid = threadIdx.x;

    // ---- per-block prep (overlapped across 192 blocks) ----
    {
        int pos = tid >> 3, i = tid & 7;
        float L = log2f(100.0f);
        float f = exp2f(-L * (float)i / 8.0f);
        float sv, cv; sincosf((float)pos * f, &sv, &cv);
        sCos[pos][i] = cv; sSin[pos][i] = sv;
        if (blockIdx.x == 0) { g_cos[pos][i] = cv; g_sin[pos][i] = sv; }
    }
    if (tid < 4) {
        int c = tid;
        const float* V  = vm + c*16;
        const float* Kc = Ks + c*9;
        float a = Kc[0] * (1.0f/512.0f);
        float b = Kc[4] * (1.0f/512.0f);
        float u = Kc[2] * (1.0f/512.0f) - 0.5f;
        float w = Kc[5] * (1.0f/512.0f) - 0.5f;
        float K4[16] = {a,0,u,0, 0,b,w,0, 0,0,1,0, 0,0,0,1};
        float Vl[16];
#pragma unroll
        for (int i = 0; i < 16; i++) Vl[i] = V[i];
        float P[16];
        mm4(K4, Vl, P);
        if (blockIdx.x == 0) {
#pragma unroll
            for (int i = 0; i < 4; i++)
#pragma unroll
                for (int jj = 0; jj < 4; jj++) {
                    g_P[c][i*4+jj]  = P[i*4+jj];
                    g_PT[c][i*4+jj] = P[jj*4+i];
                }
        }
        // invert_SE3(viewmats) * lift_K(invert_K(Ksn))
        float Sm[16];
#pragma unroll
        for (int i = 0; i < 3; i++)
#pragma unroll
            for (int jj = 0; jj < 3; jj++) Sm[i*4+jj] = Vl[jj*4+i];
#pragma unroll
        for (int i = 0; i < 3; i++)
            Sm[i*4+3] = -(Sm[i*4+0]*Vl[3] + Sm[i*4+1]*Vl[7] + Sm[i*4+2]*Vl[11]);
        Sm[12]=0.f; Sm[13]=0.f; Sm[14]=0.f; Sm[15]=1.f;
        float Ki[16] = {1.0f/a,0,-u/a,0, 0,1.0f/b,-w/b,0, 0,0,1,0, 0,0,0,1};
        float Pi[16];
        mm4(Sm, Ki, Pi);
#pragma unroll
        for (int i = 0; i < 16; i++) sPinv[c][i] = Pi[i];
    }
    __syncthreads();

    int r = blockIdx.x * 256 + tid;
    int w = tid >> 5, lane = tid & 31;
    int h = r >> 12;
    int s = r & 4095;
    int cam = s >> 10, px = s & 31, py = (s >> 5) & 31;
    float M[16];
#pragma unroll
    for (int i = 0; i < 16; i++) M[i] = sPinv[cam][i];
    size_t ibase = ((size_t)s * NH + h) * HD;

    float y[64];
    // ---- K: dim-permuted in 16-groups, fp16, coalesced row store ----
    transform_row_t(k + ibase, y, M, sCos, sSin, px, py);
    {
        uint32_t kk[32];
#pragma unroll
        for (int t = 0; t < 4; t++)
#pragma unroll
            for (int jj = 0; jj < 4; jj++) {
                int base = t*16, q = t*4 + jj;
                kk[2*q]   = packh2(y[base+2*jj],   y[base+2*jj+1]);
                kk[2*q+1] = packh2(y[base+2*jj+8], y[base+2*jj+9]);
            }
        uint4* o4 = (uint4*)(g_k + ((size_t)h*S_TOK + s)*HD);
#pragma unroll
        for (int i = 0; i < 8; i++) o4[i] = ((uint4*)kk)[i];
    }
    // ---- V: transpose through SMEM -> g_vt[h][d][s], keys permuted in 16-groups ----
    transform_row_t(v + ibase, y, M, sCos, sSin, px, py);
#pragma unroll
    for (int d = 0; d < 64; d++) vsm[w][d][lane] = __float2half(y[d]);
    __syncwarp();
    int tile = s >> 5;
#pragma unroll
    for (int hf = 0; hf < 2; hf++) {
        int d = lane + 32*hf;
        uint32_t ov[16];
#pragma unroll
        for (int tk = 0; tk < 2; tk++)
#pragma unroll
            for (int q = 0; q < 4; q++) {
                int b = tk*8 + q*2;
                __half2 e = __halves2half2(vsm[w][d][tk*16+2*q],   vsm[w][d][tk*16+2*q+1]);
                __half2 f = __halves2half2(vsm[w][d][tk*16+8+2*q], vsm[w][d][tk*16+8+2*q+1]);
                ov[b]   = *(uint32_t*)&e;
                ov[b+1] = *(uint32_t*)&f;
            }
        uint4* dst = (uint4*)(g_vt + ((size_t)h*HD + d)*S_TOK + (size_t)tile*32);
#pragma unroll
        for (int i = 0; i < 4; i++) dst[i] = ((uint4*)ov)[i];
    }
}

// ---------------------------------------------------------------------------
// fp16 m16n8k16 pipelined flash attention. Triple-buffered K/VT (cp.async),
// P packs straight from GEMM1 D registers (no permutation, no SMEM trip).
// ---------------------------------------------------------------------------

#define STAGE(BUF, T) do { \
    uint32_t kb_ = sb + K_OFF + (uint32_t)(BUF) * K_BUF_B; \
    uint32_t vb_ = sb + V_OFF + (uint32_t)(BUF) * V_BUF_B; \
    const __half* ks_ = kg2 + (size_t)(T) * (KTILE*HD); \
    const __half* vs_ = vtg + (size_t)(T) * KTILE; \
    _Pragma("unroll") \
    for (int i_ = 0; i_ < 2; i_++) { \
        int idx_ = tid + i_*128; \
        int kr_ = idx_ >> 3, kc_ = idx_ & 7; \
        cp16(kb_ + (uint32_t)(kr_*ROWB + kc_*16), ks_ + kr_*HD + kc_*8); \
        int vr_ = idx_ >> 2, vc_ = idx_ & 3; \
        cp16(vb_ + (uint32_t)(vr_*ROWB + vc_*16), vs_ + (size_t)vr_*S_TOK + vc_*8); \
    } \
    CP_COMMIT(); \
} while(0)

// SC: f32 scores [2][4][4] -> PH: fp16x2 P fragments [2][4][2]; computes rs
#define SOFTMAX_PK(SC, PH) do { \
    _Pragma("unroll") \
    for (int m_ = 0; m_ < 2; m_++) \
    _Pragma("unroll") \
    for (int hi_ = 0; hi_ < 2; hi_++) { \
        int rc_ = m_*2 + hi_; \
        float mt_ = -1e30f; \
        _Pragma("unroll") \
        for (int nb_ = 0; nb_ < 4; nb_++) { \
            mt_ = fmaxf(mt_, SC[m_][nb_][hi_*2]); \
            mt_ = fmaxf(mt_, SC[m_][nb_][hi_*2+1]); \
        } \
        mt_ = fmaxf(mt_, __shfl_xor_sync(0xffffffffu, mt_, 1)); \
        mt_ = fmaxf(mt_, __shfl_xor_sync(0xffffffffu, mt_, 2)); \
        float mn_ = fmaxf(mrow[rc_], mt_); \
        rs[rc_] = ex2(mrow[rc_] - mn_); \
        mrow[rc_] = mn_; \
        float ps_ = 0.f; \
        _Pragma("unroll") \
        for (int nb_ = 0; nb_ < 4; nb_++) { \
            float p0_ = ex2(SC[m_][nb_][hi_*2]   - mn_); \
            float p1_ = ex2(SC[m_][nb_][hi_*2+1] - mn_); \
            ps_ += p0_ + p1_; \
            PH[m_][nb_][hi_] = packh2(p0_, p1_); \
        } \
        ps_ += __shfl_xor_sync(0xffffffffu, ps_, 1); \
        ps_ += __shfl_xor_sync(0xffffffffu, ps_, 2); \
        lsum[rc_] = lsum[rc_]*rs[rc_] + ps_; \
    } \
} while(0)

#define RESCALE() do { \
    bool a1_ = (rs[0]==1.f) & (rs[1]==1.f) & (rs[2]==1.f) & (rs[3]==1.f); \
    if (!__all_sync(0xffffffffu, a1_)) { \
        _Pragma("unroll") \
        for (int m_ = 0; m_ < 2; m_++) \
        _Pragma("unroll") \
        for (int nb_ = 0; nb_ < 8; nb_++) { \
            o[m_][nb_][0] *= rs[m_*2];   o[m_][nb_][1] *= rs[m_*2]; \
            o[m_][nb_][2] *= rs[m_*2+1]; o[m_][nb_][3] *= rs[m_*2+1]; \
        } \
    } \
} while(0)

#define GEMM1(SCN, KFP) do { \
    _Pragma("unroll") \
    for (int tt_ = 0; tt_ < 4; tt_++) \
    _Pragma("unroll") \
    for (int nb_ = 0; nb_ < 4; nb_++) { \
        uint2 b_ = *(const uint2*)((KFP) + (nb_*8 + g)*ROWB + tt_*32 + 8*j); \
        mma_f16(SCN[0][nb_], qa[0][tt_], b_.x, b_.y); \
        mma_f16(SCN[1][nb_], qa[1][tt_], b_.x, b_.y); \
    } \
} while(0)

#define GEMM2(PH, VFP) do { \
    _Pragma("unroll") \
    for (int tk_ = 0; tk_ < 2; tk_++) { \
        uint32_t pa0_[4] = { PH[0][2*tk_][0], PH[0][2*tk_][1], \
                             PH[0][2*tk_+1][0], PH[0][2*tk_+1][1] }; \
        uint32_t pa1_[4] = { PH[1][2*tk_][0], PH[1][2*tk_][1], \
                             PH[1][2*tk_+1][0], PH[1][2*tk_+1][1] }; \
        _Pragma("unroll") \
        for (int nb_ = 0; nb_ < 8; nb_++) { \
            uint2 b_ = *(const uint2*)((VFP) + (nb_*8 + g)*ROWB + tk_*32 + 8*j); \
            mma_f16(o[0][nb_], pa0_, b_.x, b_.y); \
            mma_f16(o[1][nb_], pa1_, b_.x, b_.y); \
        } \
    } \
} while(0)

#define TILE_BODY(T, PHP, PHN) do { \
    CP_WAIT0(); __syncthreads(); \
    if ((T)+2 < NTILES) STAGE(bf, (T)+2); \
    const char* Kf_ = smraw + K_OFF + bn*K_BUF_B; \
    const char* Vf_ = smraw + V_OFF + bc*V_BUF_B; \
    _Pragma("unroll") \
    for (int m_ = 0; m_ < 2; m_++) \
    _Pragma("unroll") \
    for (int nb_ = 0; nb_ < 4; nb_++) \
    _Pragma("unroll") \
    for (int e_ = 0; e_ < 4; e_++) sc[m_][nb_][e_] = 0.f; \
    GEMM1(sc, Kf_); \
    RESCALE(); \
    SOFTMAX_PK(sc, PHN); \
    GEMM2(PHP, Vf_); \
    { int tb_ = bc; bc = bn; bn = bf; bf = tb_; } \
} while(0)

__global__ void __launch_bounds__(QTILE)
attn_kernel(const float* __restrict__ q, float* __restrict__ out) {
    extern __shared__ char smraw[];
    const uint32_t sb = smem_u32(smraw);

    const int tid  = threadIdx.x;
    const int w    = tid >> 5, lane = tid & 31;
    const int g    = lane >> 2, j = lane & 3;
    const int h    = blockIdx.y;
    const int s    = blockIdx.x * QTILE + tid;
    const int cam  = s >> 10, px = s & 31, py = (s >> 5) & 31;

    const __half* kg2 = g_k  + (size_t)h * S_TOK * HD;
    const __half* vtg = g_vt + (size_t)h * HD * S_TOK;

    STAGE(0, 0);
    STAGE(1, 1);

    // ---- Q transform -> QF (fp16, dim-permuted, scale*log2e folded) ----
    {
        float y[64];
        transform_row_t(q + (size_t)s * (NH*HD) + (size_t)h * HD, y, g_PT[cam],
                        g_cos, g_sin, px, py);
        const float SC = 0.18033688011112042f;  // (1/8)*log2(e)
        uint32_t qq[32];
#pragma unroll
        for (int t = 0; t < 4; t++)
#pragma unroll
            for (int jj = 0; jj < 4; jj++) {
                int base = t*16, qx = t*4 + jj;
                qq[2*qx]   = packh2(y[base+2*jj]*SC,   y[base+2*jj+1]*SC);
                qq[2*qx+1] = packh2(y[base+2*jj+8]*SC, y[base+2*jj+9]*SC);
            }
        uint4* dst = (uint4*)(smraw + QF_OFF + tid*ROWB);
#pragma unroll
        for (int i = 0; i < 8; i++) dst[i] = ((uint4*)qq)[i];
    }
    CP_WAIT1();
    __syncthreads();

    // ---- persistent Q A-fragments (LDS.64 pairs) ----
    uint32_t qa[2][4][4];
#pragma unroll
    for (int m = 0; m < 2; m++)
#pragma unroll
        for (int tt = 0; tt < 4; tt++) {
            const char* rp = smraw + QF_OFF + (w*32 + m*16 + g)*ROWB + tt*32 + 8*j;
            uint2 lo = *(const uint2*)rp;
            uint2 hi = *(const uint2*)(rp + 8*ROWB);
            qa[m][tt][0] = lo.x; qa[m][tt][1] = hi.x;
            qa[m][tt][2] = lo.y; qa[m][tt][3] = hi.y;
        }

    float o[2][8][4];
#pragma unroll
    for (int m = 0; m < 2; m++)
#pragma unroll
        for (int nb = 0; nb < 8; nb++)
#pragma unroll
            for (int e = 0; e < 4; e++) o[m][nb][e] = 0.f;
    float mrow[4] = {-1e30f, -1e30f, -1e30f, -1e30f};
    float lsum[4] = {0.f, 0.f, 0.f, 0.f};
    float rs[4];
    float sc[2][4][4];
    uint32_t phA[2][4][2], phB[2][4][2];
    int bc = 0, bn = 1, bf = 2;

    // ---- preamble: GEMM1(0) + softmax(0) into phA ----
    {
        const char* Kf_ = smraw + K_OFF;
#pragma unroll
        for (int m = 0; m < 2; m++)
#pragma unroll
            for (int nb = 0; nb < 4; nb++)
#pragma unroll
                for (int e = 0; e < 4; e++) sc[m][nb][e] = 0.f;
        GEMM1(sc, Kf_);
        SOFTMAX_PK(sc, phA);
    }

    // ---- pipelined main loop ----
#pragma unroll 1
    for (int t = 0; t < NTILES-2; t += 2) {
        TILE_BODY(t,   phA, phB);
        TILE_BODY(t+1, phB, phA);
    }
    TILE_BODY(NTILES-2, phA, phB);

    // ---- final tile: rescale + GEMM2(127) ----
    {
        const char* Vf_ = smraw + V_OFF + bc*V_BUF_B;
        RESCALE();
        GEMM2(phB, Vf_);
    }

    // ---- normalize, exchange O through SMEM (reuse K/V region), epilogue ----
    __syncthreads();
    float* QP = (float*)smraw;
    float inv[4];
#pragma unroll
    for (int rc = 0; rc < 4; rc++) inv[rc] = 1.0f / lsum[rc];
#pragma unroll
    for (int m = 0; m < 2; m++) {
        int r0 = w*32 + m*16 + g, r1 = r0 + 8;
#pragma unroll
        for (int nb = 0; nb < 8; nb++) {
            *(float2*)&QP[r0*QSTR + nb*8 + 2*j] =
                make_float2(o[m][nb][0]*inv[m*2],   o[m][nb][1]*inv[m*2]);
            *(float2*)&QP[r1*QSTR + nb*8 + 2*j] =
                make_float2(o[m][nb][2]*inv[m*2+1], o[m][nb][3]*inv[m*2+1]);
        }
    }
    __syncthreads();

    {
        float acc[64];
#pragma unroll
        for (int i = 0; i < 16; i++) {
            float4 tv = *(const float4*)&QP[(size_t)tid*QSTR + i*4];
            acc[4*i+0]=tv.x; acc[4*i+1]=tv.y; acc[4*i+2]=tv.z; acc[4*i+3]=tv.w;
        }
        float y[64];
        const float* M = g_P[cam];
#pragma unroll
        for (int gg = 0; gg < 8; gg++)
#pragma unroll
            for (int i = 0; i < 4; i++)
                y[gg*4+i] = M[i*4+0]*acc[gg*4+0] + M[i*4+1]*acc[gg*4+1]
                          + M[i*4+2]*acc[gg*4+2] + M[i*4+3]*acc[gg*4+3];
#pragma unroll
        for (int i = 0; i < 8; i++) {
            float c1 = g_cos[px][i], s1 = g_sin[px][i];
            y[32+i] = c1*acc[32+i] - s1*acc[40+i];
            y[40+i] = s1*acc[32+i] + c1*acc[40+i];
            float c2 = g_cos[py][i], s2 = g_sin[py][i];
            y[48+i] = c2*acc[48+i] - s2*acc[56+i];
            y[56+i] = s2*acc[48+i] + c2*acc[56+i];
        }
        float4* o4 = (float4*)(out + (size_t)s * (NH*HD) + (size_t)h * HD);
#pragma unroll
        for (int i = 0; i < 16; i++)
            o4[i] = make_float4(y[4*i+0], y[4*i+1], y[4*i+2], y[4*i+3]);
    }
}

// ---------------------------------------------------------------------------
extern "C" void kernel_launch(void* const* d_in, const int* in_sizes, int n_in,
                              void* d_out, int out_size) {
    const float* q  = (const float*)d_in[0];
    const float* k  = (const float*)d_in[1];
    const float* v  = (const float*)d_in[2];
    const float* vm = (const float*)d_in[3];
    const float* Ks = (const float*)d_in[4];
    float* out = (float*)d_out;

    cudaFuncSetAttribute(attn_kernel, cudaFuncAttributeMaxDynamicSharedMemorySize, SMEM_BYTES);

    transform_kv_kernel<<<NROWS / 256, 256>>>(k, v, vm, Ks);
    attn_kernel<<<dim3(S_TOK / QTILE, NH), QTILE, SMEM_BYTES>>>(q, out);
}